// round 1
// baseline (speedup 1.0000x reference)
#include <cuda_runtime.h>
#include <stdint.h>

// Problem dims (fixed by the dataset):
//   weights   [T=8]          fp32
//   bond_src  [B=1024,E=512] int32  (values 0..254, +1 applied)
//   bond_dst  [B=1024,E=512] int32
//   bond_type [B=1024,E=512] int32
//   num_nodes scalar (=256)
//   out       [B,256,256]    fp32  -> 256 MiB, HBM-write-bound
static constexpr int Bb    = 1024;
static constexpr int E     = 512;
static constexpr int Nn    = 256;
static constexpr int CELLS = Nn * Nn;       // 65536 floats per batch slice
static constexpr int TS    = 2048;          // hash slots (load factor <= 0.5)
static constexpr int THREADS = 512;

// Open-addressed smem hash. Entry: key(16b high) | prio(16b low). 0 == empty.
// key in [257, 65535] so a valid entry is never 0. prio in [1, 1024].
__device__ __forceinline__ void ht_insert(uint32_t* table, uint32_t key, uint32_t prio) {
    uint32_t entry = (key << 16) | prio;
    uint32_t h = (key * 2654435761u) >> (32 - 11);   // 11 bits -> [0, 2048)
    #pragma unroll 1
    while (true) {
        uint32_t cur = table[h];
        if (cur == 0u) {
            uint32_t old = atomicCAS(&table[h], 0u, entry);
            if (old == 0u) return;                   // claimed empty slot
            cur = old;                               // lost race; inspect winner
        }
        if ((cur >> 16) == key) {                    // same cell -> max priority wins
            atomicMax(&table[h], entry);             // high bits equal, so packed max == prio max
            return;
        }
        h = (h + 1) & (TS - 1);                      // linear probe
    }
}

__device__ __forceinline__ uint32_t ht_lookup(const uint32_t* table, uint32_t key) {
    uint32_t h = (key * 2654435761u) >> (32 - 11);
    #pragma unroll 1
    while (true) {
        uint32_t cur = table[h];
        if ((cur >> 16) == key) return cur & 0xFFFFu;
        h = (h + 1) & (TS - 1);
    }
}

__global__ __launch_bounds__(THREADS, 2)
void bond_weight_kernel(const float* __restrict__ weights,
                        const int*   __restrict__ bond_src,
                        const int*   __restrict__ bond_dst,
                        const int*   __restrict__ bond_type,
                        float*       __restrict__ out)
{
    __shared__ uint32_t table[TS];

    const int b = blockIdx.x;
    const int t = threadIdx.x;

    // ---- clear hash table (8 KB) ----
    #pragma unroll
    for (int i = 0; i < TS / THREADS; i++)
        table[t + i * THREADS] = 0u;

    // ---- load this thread's edge & start dedup inserts ----
    const int  eidx = b * E + t;            // 512 threads == 512 edges per batch
    const int  s = bond_src[eidx] + 1;      // 1..255
    const int  d = bond_dst[eidx] + 1;      // 1..255
    const float w = weights[bond_type[eidx]];

    const uint32_t key1 = (uint32_t)(s * Nn + d);   // pass 0: out[b, src, dst]
    const uint32_t key2 = (uint32_t)(d * Nn + s);   // pass 1: out[b, dst, src]
    const uint32_t prio1 = (uint32_t)(t + 1);       // sequential-application order:
    const uint32_t prio2 = (uint32_t)(E + t + 1);   // pass1 beats pass0; higher e wins

    // ---- zero this batch's 256 KB slice with float4 stores ----
    float4* o4 = reinterpret_cast<float4*>(out + (size_t)b * CELLS);
    const float4 z = make_float4(0.f, 0.f, 0.f, 0.f);
    #pragma unroll
    for (int i = 0; i < (CELLS / 4) / THREADS; i++)   // 16384 float4 / 512 thr = 32 each
        o4[t + i * THREADS] = z;

    __syncthreads();     // table cleared before inserts (zero-fill stores can still drain)

    ht_insert(table, key1, prio1);
    ht_insert(table, key2, prio2);

    __syncthreads();     // all inserts done; zero-fill complete before sparse overwrite

    // ---- emit only the winning write per cell (deterministic, race-free) ----
    float* o = out + (size_t)b * CELLS;
    if (ht_lookup(table, key1) == prio1) o[key1] = w;
    if (ht_lookup(table, key2) == prio2) o[key2] = w;
}

extern "C" void kernel_launch(void* const* d_in, const int* in_sizes, int n_in,
                              void* d_out, int out_size)
{
    const float* weights   = (const float*)d_in[0];
    const int*   bond_src  = (const int*)  d_in[1];
    const int*   bond_dst  = (const int*)  d_in[2];
    const int*   bond_type = (const int*)  d_in[3];
    // d_in[4] = num_nodes (compile-time 256 here)
    float* out = (float*)d_out;

    bond_weight_kernel<<<Bb, THREADS>>>(weights, bond_src, bond_dst, bond_type, out);
}